// round 5
// baseline (speedup 1.0000x reference)
#include <cuda_runtime.h>

#define H      128
#define W      128
#define NLAM   128
#define BATCH  16
#define NK     4
#define HP     192
#define WP     192
#define RPW    8           // output rows per warp

// scratch accumulator: (B*NK, HP, WP) = 9.4 MB
__device__ float g_acc[BATCH * NK * HP * WP];

// ---------------------------------------------------------------------------
// Kernel 1: per-(b,k) accumulate over wavelengths of uniformly-shifted slices.
// Block (32,8). Each lane owns 2 consecutive output cols (float2); a warp owns
// 64 cols x 8 rows. Grid (3, 3, B*NK).
//
// out(y,x) += fy*h(y-33-ny) + gy*h(y-32-ny),
//   h(r, x) = fx*in[r][x-33-nx] + gx*in[r][x-32-nx]
// Loads: per row, 2x LDG.64 at even base ta = (t & ~1); warp-uniform parity
// o = t & 1 selects the 3 tap values out of the 4 loaded.
// ---------------------------------------------------------------------------
__global__ __launch_bounds__(256) void accum_kernel(
    const float* __restrict__ cube,   // (B, NLAM, H, W)
    const float* __restrict__ dx,     // (NK, NLAM)
    const float* __restrict__ dy)     // (NK, NLAM)
{
    __shared__ int    s_nx[NLAM], s_ny[NLAM];
    __shared__ float4 s_w[NLAM];      // (fx, gx, fy, gy)

    const int bz = blockIdx.z;
    const int b  = bz >> 2;
    const int k  = bz & 3;

    const int tid = threadIdx.y * 32 + threadIdx.x;
    if (tid < NLAM) {
        float dxv = dx[k * NLAM + tid];
        float dyv = dy[k * NLAM + tid];
        float nxf = floorf(dxv), nyf = floorf(dyv);
        s_nx[tid] = (int)nxf;
        s_ny[tid] = (int)nyf;
        float fx = dxv - nxf, fy = dyv - nyf;
        s_w[tid] = make_float4(fx, 1.0f - fx, fy, 1.0f - fy);
    }
    __syncthreads();

    const int lane = threadIdx.x;
    const int x0w  = blockIdx.x * 64;                       // block col base
    const int y0   = (blockIdx.y * 8 + threadIdx.y) * RPW;  // warp row base

    float a0[RPW], a1[RPW];
    #pragma unroll
    for (int i = 0; i < RPW; ++i) { a0[i] = 0.0f; a1[i] = 0.0f; }

    const float* cb = cube + (size_t)b * NLAM * H * W;

    for (int l = 0; l < NLAM; ++l) {
        const int nx  = s_nx[l];
        const int ny  = s_ny[l];
        const int t   = x0w - 33 - nx;   // needed cols [t, t+64]
        const int ry0 = y0  - 33 - ny;   // needed rows [ry0, ry0+RPW]

        // fully out-of-bounds lambda contributes exactly zero
        if (t > W - 1 || t + 64 < 0 || ry0 > H - 1 || ry0 + RPW < 0) continue;

        const float4 wv = s_w[l];
        const float fx = wv.x, gx = wv.y, fy = wv.z, gy = wv.w;
        const float* sl = cb + l * (H * W);
        const int o  = t & 1;            // warp-uniform parity
        const int ta = t - o;            // even base
        const int ca = ta + 2 * lane;    // this lane's load base col

        const bool interior = (t >= 0) & (t + 64 <= W - 1) &
                              (ry0 >= 0) & (ry0 + RPW <= H - 1);

        float hp0, hp1;

        if (interior) {
            const float* rp = sl + ry0 * W + ca;
            {
                float2 A  = __ldg((const float2*)rp);
                float2 Bv = __ldg((const float2*)(rp + 2));
                float v0 = o ? A.y  : A.x;
                float v1 = o ? Bv.x : A.y;
                float v2 = o ? Bv.y : Bv.x;
                hp0 = fx * v0 + gx * v1;
                hp1 = fx * v1 + gx * v2;
            }
            #pragma unroll
            for (int j = 1; j <= RPW; ++j) {
                const float* rj = rp + j * W;
                float2 A  = __ldg((const float2*)rj);
                float2 Bv = __ldg((const float2*)(rj + 2));
                float v0 = o ? A.y  : A.x;
                float v1 = o ? Bv.x : A.y;
                float v2 = o ? Bv.y : Bv.x;
                float hc0 = fx * v0 + gx * v1;
                float hc1 = fx * v1 + gx * v2;
                a0[j - 1] += fy * hp0 + gy * hc0;
                a1[j - 1] += fy * hp1 + gy * hc1;
                hp0 = hc0; hp1 = hc1;
            }
        } else {
            // edge: per-element predicated scalar loads
            {
                int row = ry0;
                bool rv = ((unsigned)row < (unsigned)H);
                const float* rj = sl + row * W;
                float A0 = (rv && (unsigned)(ca)     < (unsigned)W) ? __ldg(rj + ca)     : 0.0f;
                float A1 = (rv && (unsigned)(ca + 1) < (unsigned)W) ? __ldg(rj + ca + 1) : 0.0f;
                float B0 = (rv && (unsigned)(ca + 2) < (unsigned)W) ? __ldg(rj + ca + 2) : 0.0f;
                float B1 = (rv && (unsigned)(ca + 3) < (unsigned)W) ? __ldg(rj + ca + 3) : 0.0f;
                float v0 = o ? A1 : A0;
                float v1 = o ? B0 : A1;
                float v2 = o ? B1 : B0;
                hp0 = fx * v0 + gx * v1;
                hp1 = fx * v1 + gx * v2;
            }
            #pragma unroll
            for (int j = 1; j <= RPW; ++j) {
                int row = ry0 + j;
                bool rv = ((unsigned)row < (unsigned)H);
                const float* rj = sl + row * W;
                float A0 = (rv && (unsigned)(ca)     < (unsigned)W) ? __ldg(rj + ca)     : 0.0f;
                float A1 = (rv && (unsigned)(ca + 1) < (unsigned)W) ? __ldg(rj + ca + 1) : 0.0f;
                float B0 = (rv && (unsigned)(ca + 2) < (unsigned)W) ? __ldg(rj + ca + 2) : 0.0f;
                float B1 = (rv && (unsigned)(ca + 3) < (unsigned)W) ? __ldg(rj + ca + 3) : 0.0f;
                float v0 = o ? A1 : A0;
                float v1 = o ? B0 : A1;
                float v2 = o ? B1 : B0;
                float hc0 = fx * v0 + gx * v1;
                float hc1 = fx * v1 + gx * v2;
                a0[j - 1] += fy * hp0 + gy * hc0;
                a1[j - 1] += fy * hp1 + gy * hc1;
                hp0 = hc0; hp1 = hc1;
            }
        }
    }

    float* ap = g_acc + ((size_t)bz * HP + y0) * WP + x0w + 2 * lane;
    #pragma unroll
    for (int i = 0; i < RPW; ++i)
        *(float2*)(ap + i * WP) = make_float2(a0[i], a1[i]);
}

// ---------------------------------------------------------------------------
// Kernel 2: 7x7 PSF convolution (same padding, zeros), acc -> out.
// Block: (32, 8), output tile 32x32 (each thread 4 consecutive rows).
// Grid: (6, 6, B*NK).
// ---------------------------------------------------------------------------
__global__ __launch_bounds__(256) void conv_kernel(
    const float* __restrict__ psf,    // (7,7)
    float* __restrict__ out)          // (B, NK, HP, WP)
{
    __shared__ float s[38 * 40];
    __shared__ float sp[49];

    const int bz = blockIdx.z;
    const float* ap = g_acc + (size_t)bz * HP * WP;

    const int tid = threadIdx.y * 32 + threadIdx.x;
    if (tid < 49) sp[tid] = psf[tid];

    const int x0 = blockIdx.x * 32;
    const int y0 = blockIdx.y * 32;

    for (int i = tid; i < 38 * 38; i += 256) {
        int r = i / 38, c = i % 38;
        int gy = y0 + r - 3;
        int gx = x0 + c - 3;
        s[r * 40 + c] = (((unsigned)gy < (unsigned)HP) && ((unsigned)gx < (unsigned)WP))
                            ? ap[gy * WP + gx] : 0.0f;
    }
    __syncthreads();

    float w[49];
    #pragma unroll
    for (int i = 0; i < 49; ++i) w[i] = sp[i];

    const int tx = threadIdx.x;
    const int rbase = threadIdx.y * 4;

    float a0 = 0.f, a1 = 0.f, a2 = 0.f, a3 = 0.f;
    #pragma unroll
    for (int rr = 0; rr < 10; ++rr) {
        #pragma unroll
        for (int v = 0; v < 7; ++v) {
            float xv = s[(rbase + rr) * 40 + tx + v];
            if (rr <= 6)            a0 += w[rr * 7 + v] * xv;
            if (rr >= 1 && rr <= 7) a1 += w[(rr - 1) * 7 + v] * xv;
            if (rr >= 2 && rr <= 8) a2 += w[(rr - 2) * 7 + v] * xv;
            if (rr >= 3)            a3 += w[(rr - 3) * 7 + v] * xv;
        }
    }

    float* op = out + ((size_t)bz * HP + y0 + rbase) * WP + x0 + tx;
    op[0 * WP] = a0;
    op[1 * WP] = a1;
    op[2 * WP] = a2;
    op[3 * WP] = a3;
}

extern "C" void kernel_launch(void* const* d_in, const int* in_sizes, int n_in,
                              void* d_out, int out_size)
{
    const float* cube = (const float*)d_in[0];
    const float* psf  = (const float*)d_in[1];
    const float* dx   = (const float*)d_in[2];
    const float* dy   = (const float*)d_in[3];
    float* out = (float*)d_out;

    dim3 gb(3, 3, BATCH * NK), tb(32, 8);
    accum_kernel<<<gb, tb>>>(cube, dx, dy);

    dim3 gc(6, 6, BATCH * NK), tc(32, 8);
    conv_kernel<<<gc, tc>>>(psf, out);
}

// round 6
// speedup vs baseline: 1.6421x; 1.6421x over previous
#include <cuda_runtime.h>

#define H      128
#define W      128
#define NLAM   128
#define BATCH  16
#define NK     4
#define HP     192
#define WP     192

#define HALFSZ (BATCH * NK * HP * WP)
// two half-lambda accumulators: 2 x 9.4 MB
__device__ float g_acc[2 * HALFSZ];

// ---------------------------------------------------------------------------
// Kernel 1: accumulate shifted slices over one half of the wavelength range.
// Block (32,8): lane owns 2 consecutive output cols; warp owns 64 cols x 4
// rows. Grid (3, 6, 128): z = (b*4 + k)*2 + lambda_half. 2304 blocks.
//
// out(y,x) += fy*h(ry) + gy*h(ry+1),  h(r) = fx*in[r][x-33-nx] + gx*in[r][x-32-nx]
// ---------------------------------------------------------------------------
__global__ __launch_bounds__(256) void accum_kernel(
    const float* __restrict__ cube,   // (B, NLAM, H, W)
    const float* __restrict__ dx,     // (NK, NLAM)
    const float* __restrict__ dy)     // (NK, NLAM)
{
    __shared__ int    s_nx[64], s_ny[64];
    __shared__ float4 s_w[64];        // (fx, gx, fy, gy)

    const int bz  = blockIdx.z;
    const int lh  = bz & 1;           // lambda half
    const int bk  = bz >> 1;          // (b*4 + k)
    const int b   = bk >> 2;
    const int k   = bk & 3;
    const int l0  = lh * 64;

    const int tid = threadIdx.y * 32 + threadIdx.x;
    if (tid < 64) {
        float dxv = dx[k * NLAM + l0 + tid];
        float dyv = dy[k * NLAM + l0 + tid];
        float nxf = floorf(dxv), nyf = floorf(dyv);
        s_nx[tid] = (int)nxf;
        s_ny[tid] = (int)nyf;
        float fx = dxv - nxf, fy = dyv - nyf;
        s_w[tid] = make_float4(fx, 1.0f - fx, fy, 1.0f - fy);
    }
    __syncthreads();

    const int lane = threadIdx.x;
    const int x0w  = blockIdx.x * 64;                    // block col base
    const int y0   = blockIdx.y * 32 + threadIdx.y * 4;  // warp row base

    float a0[4], a1[4];
    #pragma unroll
    for (int i = 0; i < 4; ++i) { a0[i] = 0.0f; a1[i] = 0.0f; }

    const float* cb = cube + ((size_t)b * NLAM + l0) * (H * W);

    for (int l = 0; l < 64; ++l) {
        const int nx  = s_nx[l];
        const int ny  = s_ny[l];
        const int t   = x0w - 33 - nx;   // needed cols [t, t+64]
        const int ry0 = y0  - 33 - ny;   // needed rows [ry0, ry0+4]

        // fully out-of-bounds lambda contributes exactly zero
        if (t > W - 1 || t + 64 < 0 || ry0 > H - 1 || ry0 + 4 < 0) continue;

        const float4 wv = s_w[l];
        const float fx = wv.x, gx = wv.y, fy = wv.z, gy = wv.w;
        const float* sl = cb + l * (H * W);

        const int o  = t & 1;            // warp-uniform parity
        const int ta = t - o;            // even (8B-aligned) base
        const int ca = ta + 2 * lane;

        const bool interior = (ta >= 0) & (t <= W - 1 - 64) &
                              (ry0 >= 0) & (ry0 <= H - 5);   // warp-uniform

        float hp0, hp1;

        if (interior) {
            const float* rp = sl + ry0 * W + ca;
            if (o == 0) {
                // taps: A.x, A.y, c
                {
                    float2 A = __ldg((const float2*)rp);
                    float  c = __ldg(rp + 2);
                    hp0 = fx * A.x + gx * A.y;
                    hp1 = fx * A.y + gx * c;
                }
                #pragma unroll
                for (int j = 1; j <= 4; ++j) {
                    const float* rj = rp + j * W;
                    float2 A = __ldg((const float2*)rj);
                    float  c = __ldg(rj + 2);
                    float hc0 = fx * A.x + gx * A.y;
                    float hc1 = fx * A.y + gx * c;
                    a0[j - 1] += fy * hp0 + gy * hc0;
                    a1[j - 1] += fy * hp1 + gy * hc1;
                    hp0 = hc0; hp1 = hc1;
                }
            } else {
                // taps: A.y, B.x, B.y
                {
                    float2 A = __ldg((const float2*)rp);
                    float2 B = __ldg((const float2*)(rp + 2));
                    hp0 = fx * A.y + gx * B.x;
                    hp1 = fx * B.x + gx * B.y;
                }
                #pragma unroll
                for (int j = 1; j <= 4; ++j) {
                    const float* rj = rp + j * W;
                    float2 A = __ldg((const float2*)rj);
                    float2 B = __ldg((const float2*)(rj + 2));
                    float hc0 = fx * A.y + gx * B.x;
                    float hc1 = fx * B.x + gx * B.y;
                    a0[j - 1] += fy * hp0 + gy * hc0;
                    a1[j - 1] += fy * hp1 + gy * hc1;
                    hp0 = hc0; hp1 = hc1;
                }
            }
        } else {
            // edge: per-element predicated scalar loads at exact tap columns
            const int c0 = t + 2 * lane;
            const bool cv0 = ((unsigned)c0       < (unsigned)W);
            const bool cv1 = ((unsigned)(c0 + 1) < (unsigned)W);
            const bool cv2 = ((unsigned)(c0 + 2) < (unsigned)W);
            {
                bool rv = ((unsigned)ry0 < (unsigned)H);
                const float* rj = sl + ry0 * W + c0;
                float v0 = (rv && cv0) ? __ldg(rj)     : 0.0f;
                float v1 = (rv && cv1) ? __ldg(rj + 1) : 0.0f;
                float v2 = (rv && cv2) ? __ldg(rj + 2) : 0.0f;
                hp0 = fx * v0 + gx * v1;
                hp1 = fx * v1 + gx * v2;
            }
            #pragma unroll
            for (int j = 1; j <= 4; ++j) {
                int row = ry0 + j;
                bool rv = ((unsigned)row < (unsigned)H);
                const float* rj = sl + row * W + c0;
                float v0 = (rv && cv0) ? __ldg(rj)     : 0.0f;
                float v1 = (rv && cv1) ? __ldg(rj + 1) : 0.0f;
                float v2 = (rv && cv2) ? __ldg(rj + 2) : 0.0f;
                float hc0 = fx * v0 + gx * v1;
                float hc1 = fx * v1 + gx * v2;
                a0[j - 1] += fy * hp0 + gy * hc0;
                a1[j - 1] += fy * hp1 + gy * hc1;
                hp0 = hc0; hp1 = hc1;
            }
        }
    }

    float* ap = g_acc + (size_t)lh * HALFSZ + ((size_t)bk * HP + y0) * WP + x0w + 2 * lane;
    #pragma unroll
    for (int i = 0; i < 4; ++i)
        *(float2*)(ap + i * WP) = make_float2(a0[i], a1[i]);
}

// ---------------------------------------------------------------------------
// Kernel 2: 7x7 PSF convolution (same padding, zeros), (acc0+acc1) -> out.
// Block: (32, 8), output tile 32x32. Grid: (6, 6, B*NK).
// ---------------------------------------------------------------------------
__global__ __launch_bounds__(256) void conv_kernel(
    const float* __restrict__ psf,    // (7,7)
    float* __restrict__ out)          // (B, NK, HP, WP)
{
    __shared__ float s[38 * 40];
    __shared__ float sp[49];

    const int bz = blockIdx.z;
    const float* ap0 = g_acc + (size_t)bz * HP * WP;
    const float* ap1 = ap0 + HALFSZ;

    const int tid = threadIdx.y * 32 + threadIdx.x;
    if (tid < 49) sp[tid] = psf[tid];

    const int x0 = blockIdx.x * 32;
    const int y0 = blockIdx.y * 32;

    for (int i = tid; i < 38 * 38; i += 256) {
        int r = i / 38, c = i % 38;
        int gy = y0 + r - 3;
        int gx = x0 + c - 3;
        bool ok = ((unsigned)gy < (unsigned)HP) && ((unsigned)gx < (unsigned)WP);
        int idx = gy * WP + gx;
        s[r * 40 + c] = ok ? (ap0[idx] + ap1[idx]) : 0.0f;
    }
    __syncthreads();

    float w[49];
    #pragma unroll
    for (int i = 0; i < 49; ++i) w[i] = sp[i];

    const int tx = threadIdx.x;
    const int rbase = threadIdx.y * 4;

    float a0 = 0.f, a1 = 0.f, a2 = 0.f, a3 = 0.f;
    #pragma unroll
    for (int rr = 0; rr < 10; ++rr) {
        #pragma unroll
        for (int v = 0; v < 7; ++v) {
            float xv = s[(rbase + rr) * 40 + tx + v];
            if (rr <= 6)            a0 += w[rr * 7 + v] * xv;
            if (rr >= 1 && rr <= 7) a1 += w[(rr - 1) * 7 + v] * xv;
            if (rr >= 2 && rr <= 8) a2 += w[(rr - 2) * 7 + v] * xv;
            if (rr >= 3)            a3 += w[(rr - 3) * 7 + v] * xv;
        }
    }

    float* op = out + ((size_t)bz * HP + y0 + rbase) * WP + x0 + tx;
    op[0 * WP] = a0;
    op[1 * WP] = a1;
    op[2 * WP] = a2;
    op[3 * WP] = a3;
}

extern "C" void kernel_launch(void* const* d_in, const int* in_sizes, int n_in,
                              void* d_out, int out_size)
{
    const float* cube = (const float*)d_in[0];
    const float* psf  = (const float*)d_in[1];
    const float* dx   = (const float*)d_in[2];
    const float* dy   = (const float*)d_in[3];
    float* out = (float*)d_out;

    dim3 gb(3, 6, BATCH * NK * 2), tb(32, 8);
    accum_kernel<<<gb, tb>>>(cube, dx, dy);

    dim3 gc(6, 6, BATCH * NK), tc(32, 8);
    conv_kernel<<<gc, tc>>>(psf, out);
}